// round 10
// baseline (speedup 1.0000x reference)
#include <cuda_runtime.h>
#include <cuda_fp16.h>
#include <cstdint>

// Problem constants (B=2, H=8, S=2048, D=2048)
#define N_ELEM   67108864    // elements per input tensor
#define N0       33554432    // elements in x[0]
#define K_IDX    33218888u   // exact f32 quantile index of |x[0]| ascending
#define SDIM     2048
#define NBATCH   16
#define GELEMS   (SDIM * SDIM)   // elements per batch slice

// ===================== scratch: fp16 tensors (linear) =======================
__device__ __align__(1024) __half g_Ahi[N_ELEM];   // [g][m][k]  fp16(x1)
__device__ __align__(1024) __half g_Bthi[N_ELEM];  // [g][n][k]  fp16(x2^T)

// ===================== stats state (re-initialized per launch) ==============
__device__ unsigned g_hist[2][256];
__device__ unsigned g_pref[2];
__device__ unsigned g_krem[2];
__device__ unsigned g_taub[2];
__device__ unsigned g_maxres[2];
__device__ float    g_scale[2];

__global__ void k_init() {
    int i = threadIdx.x;
    g_hist[0][i] = 0; g_hist[1][i] = 0;
    if (i < 2) { g_pref[i] = 0; g_krem[i] = K_IDX; g_maxres[i] = 0; }
}

__global__ void __launch_bounds__(256) k_hist(const float4* __restrict__ x1,
                                              const float4* __restrict__ x2,
                                              int shift) {
    const int t = blockIdx.y;
    const float4* __restrict__ x = t ? x2 : x1;
    __shared__ unsigned sh[256];
    const int tid = threadIdx.x;
    sh[tid] = 0;
    __syncthreads();
    const unsigned pref = g_pref[t];
    const int n4 = N0 / 4;
    const int stride = gridDim.x * blockDim.x;
    for (int i = blockIdx.x * blockDim.x + tid; i < n4; i += stride) {
        float4 v = x[i];
        const float* f = reinterpret_cast<const float*>(&v);
        #pragma unroll
        for (int j = 0; j < 4; j++) {
            unsigned u = __float_as_uint(f[j]) & 0x7fffffffu;
            bool ok = (shift == 24) || ((u >> (shift + 8)) == pref);
            unsigned bal = __ballot_sync(0xffffffffu, ok);
            if (ok) {
                unsigned b = (u >> shift) & 255u;
                unsigned peers = __match_any_sync(bal, b);
                if ((__ffs(peers) - 1) == (tid & 31))
                    atomicAdd(&sh[b], __popc(peers));
            }
        }
    }
    __syncthreads();
    if (sh[tid]) atomicAdd(&g_hist[t][tid], sh[tid]);
}

__global__ void k_scan(int shift) {
    const int tid = threadIdx.x;
    if (tid < 2) {
        const int t = tid;
        unsigned k = g_krem[t], c = 0, chosen = 255;
        for (int b = 0; b < 256; b++) {
            unsigned h = g_hist[t][b];
            if (c + h > k) { chosen = (unsigned)b; break; }
            c += h;
        }
        g_krem[t] = k - c;
        unsigned p = (g_pref[t] << 8) | chosen;
        g_pref[t] = p;
        if (shift == 0) g_taub[t] = p;
    }
    __syncthreads();
    g_hist[0][tid] = 0; g_hist[1][tid] = 0;
}

__global__ void __launch_bounds__(256) k_maxres(const float4* __restrict__ x1,
                                                const float4* __restrict__ x2) {
    const int t = blockIdx.y;
    const float4* __restrict__ x = t ? x2 : x1;
    const unsigned taub = g_taub[t];
    const int tid = threadIdx.x;
    unsigned m = 0;
    const int n4 = N_ELEM / 4;
    const int stride = gridDim.x * blockDim.x;
    for (int i = blockIdx.x * blockDim.x + tid; i < n4; i += stride) {
        float4 v = x[i];
        const float* f = reinterpret_cast<const float*>(&v);
        #pragma unroll
        for (int j = 0; j < 4; j++) {
            unsigned u = __float_as_uint(f[j]) & 0x7fffffffu;
            if (u < taub) m = max(m, u);
        }
    }
    m = __reduce_max_sync(0xffffffffu, m);
    __shared__ unsigned sm[8];
    if ((tid & 31) == 0) sm[tid >> 5] = m;
    __syncthreads();
    if (tid == 0) {
        #pragma unroll
        for (int w = 1; w < 8; w++) m = max(m, sm[w]);
        atomicMax(&g_maxres[t], m);
    }
}

__global__ void k_scale() {
    int t = threadIdx.x;
    if (t < 2) g_scale[t] = __fdiv_rn(__uint_as_float(g_maxres[t]), 127.0f);
}

__global__ void __launch_bounds__(256) k_quant(const float4* __restrict__ x1,
                                               const float4* __restrict__ x2,
                                               float4* __restrict__ out) {
    const int t = blockIdx.y;
    const float4* __restrict__ x = t ? x2 : x1;
    float4* __restrict__ o = out + (size_t)(1 + t) * (N_ELEM / 4);
    const float tau = __uint_as_float(g_taub[t]);
    const float scale = g_scale[t];
    const int n4 = N_ELEM / 4;
    const int stride = gridDim.x * blockDim.x;
    for (int i = blockIdx.x * blockDim.x + threadIdx.x; i < n4; i += stride) {
        float4 v = x[i];
        float* f = reinterpret_cast<float*>(&v);
        #pragma unroll
        for (int j = 0; j < 4; j++) {
            float a = fabsf(f[j]);
            if (a < tau) {
                float q = rintf(__fdiv_rn(f[j], scale));
                q = fminf(fmaxf(q, -128.0f), 127.0f);
                f[j] = q * scale;
            }
        }
        o[i] = v;
    }
}

// half2 -> u32 bit cast
__device__ __forceinline__ uint32_t h2_as_u32(__half2 h) {
    union { __half2 h; uint32_t u; } c;
    c.h = h;
    return c.u;
}

// ===== A: f32 slice g -> fp16 (linear) ======================================
__global__ void __launch_bounds__(256) k_convA(const float4* __restrict__ x, int g) {
    const float4* __restrict__ xs = x + (size_t)g * (GELEMS / 4);
    uint4* __restrict__ dst = reinterpret_cast<uint4*>(g_Ahi + (size_t)g * GELEMS);
    const int stride = gridDim.x * blockDim.x;
    for (int i = blockIdx.x * blockDim.x + threadIdx.x; i < GELEMS / 8; i += stride) {
        float4 v0 = xs[2 * i], v1 = xs[2 * i + 1];
        uint32_t h[4];
        h[0] = h2_as_u32(__floats2half2_rn(v0.x, v0.y));
        h[1] = h2_as_u32(__floats2half2_rn(v0.z, v0.w));
        h[2] = h2_as_u32(__floats2half2_rn(v1.x, v1.y));
        h[3] = h2_as_u32(__floats2half2_rn(v1.z, v1.w));
        dst[i] = make_uint4(h[0], h[1], h[2], h[3]);
    }
}

// ===== B: f32 slice g [k][n] -> transposed fp16 [n][k] ======================
__global__ void __launch_bounds__(256) k_convB(const float* __restrict__ x, int g) {
    __shared__ float t[32][33];
    const float* B = x + (size_t)g * GELEMS;
    const int n0 = blockIdx.x * 32, k0 = blockIdx.y * 32;
    const int tx = threadIdx.x, ty = threadIdx.y;
    #pragma unroll
    for (int j = 0; j < 32; j += 8)
        t[ty + j][tx] = B[(size_t)(k0 + ty + j) * SDIM + n0 + tx];
    __syncthreads();
    #pragma unroll
    for (int j = 0; j < 32; j += 8) {
        int n = n0 + ty + j, k = k0 + tx;
        g_Bthi[(size_t)g * GELEMS + (size_t)n * SDIM + k] =
            __float2half_rn(t[tx][ty + j]);
    }
}

// ===== tensor-core GEMM via mma.sync (HMMA), single fp16 term ===============
// CTA 128x128, BK=32, 3-stage cp.async pipeline, 4 warps (2m x 2n),
// warp tile 64x64, mma.m16n8k16, 1 syncthreads per k-iter.
// Swizzle: 16B unit u of row r stored at u ^ ((r>>1)&3).
#define BM 128
#define BN 128
#define BK 32
#define KSTEPS 64    // 2048 / BK
#define STAGES 3

__device__ __forceinline__ uint32_t smem_u32(const void* p) {
    uint32_t a;
    asm("{ .reg .u64 t; cvta.to.shared.u64 t, %1; cvt.u32.u64 %0, t; }" : "=r"(a) : "l"(p));
    return a;
}
__device__ __forceinline__ void cp_async16(uint32_t dst, const void* src) {
    asm volatile("cp.async.cg.shared.global [%0], [%1], 16;"
                 :: "r"(dst), "l"(__cvta_generic_to_global(src)) : "memory");
}
__device__ __forceinline__ void ldsm_x4(uint32_t* r, uint32_t addr) {
    asm volatile("ldmatrix.sync.aligned.m8n8.x4.shared.b16 {%0,%1,%2,%3}, [%4];"
                 : "=r"(r[0]), "=r"(r[1]), "=r"(r[2]), "=r"(r[3]) : "r"(addr));
}
__device__ __forceinline__ void mma16816(float* d, const uint32_t* a, uint32_t b0, uint32_t b1) {
    asm volatile("mma.sync.aligned.m16n8k16.row.col.f32.f16.f16.f32 "
                 "{%0,%1,%2,%3}, {%4,%5,%6,%7}, {%8,%9}, {%0,%1,%2,%3};"
                 : "+f"(d[0]), "+f"(d[1]), "+f"(d[2]), "+f"(d[3])
                 : "r"(a[0]), "r"(a[1]), "r"(a[2]), "r"(a[3]), "r"(b0), "r"(b1));
}

__global__ void __launch_bounds__(128, 2) k_gemm_mma(float* __restrict__ C0, int g) {
    __shared__ __align__(1024) __half As[STAGES][BM * BK];  // 3 x 8KB
    __shared__ __align__(1024) __half Bs[STAGES][BN * BK];  // 3 x 8KB

    const int tid = threadIdx.x, lane = tid & 31, w = tid >> 5;
    const int wm = w >> 1, wn = w & 1;
    const int bm = blockIdx.y, bn = blockIdx.x;
    const size_t gbase = (size_t)g * GELEMS;

    const uint32_t sA = smem_u32(As), sB = smem_u32(Bs);

    float acc[4][8][4];
    #pragma unroll
    for (int i = 0; i < 4; i++)
        #pragma unroll
        for (int j = 0; j < 8; j++)
            #pragma unroll
            for (int q = 0; q < 4; q++) acc[i][j][q] = 0.0f;

    const int ldRow = tid >> 2, ldUnit = tid & 3;   // 32 rows x 4 units per pass

    auto issue = [&](int kt, int st) {
        const __half* Abase = g_Ahi  + gbase + (size_t)(bm * 128) * SDIM + kt * 32;
        const __half* Bbase = g_Bthi + gbase + (size_t)(bn * 128) * SDIM + kt * 32;
        #pragma unroll
        for (int it = 0; it < 4; it++) {
            const int r = ldRow + it * 32;
            const uint32_t du = (uint32_t)(ldUnit ^ ((r >> 1) & 3));
            cp_async16(sA + (uint32_t)st * (BM * BK * 2) + (uint32_t)r * 64 + du * 16,
                       Abase + (size_t)r * SDIM + ldUnit * 8);
            cp_async16(sB + (uint32_t)st * (BN * BK * 2) + (uint32_t)r * 64 + du * 16,
                       Bbase + (size_t)r * SDIM + ldUnit * 8);
        }
        asm volatile("cp.async.commit_group;" ::: "memory");
    };

    issue(0, 0);
    issue(1, 1);

    for (int kt = 0; kt < KSTEPS; kt++) {
        if (kt < KSTEPS - 1)
            asm volatile("cp.async.wait_group 1;" ::: "memory");
        else
            asm volatile("cp.async.wait_group 0;" ::: "memory");
        __syncthreads();   // stage kt%3 visible to all; all reads of kt-1 done

        const int st = kt % STAGES;
        const uint32_t aSt = sA + (uint32_t)st * (BM * BK * 2);
        const uint32_t bSt = sB + (uint32_t)st * (BN * BK * 2);
        #pragma unroll
        for (int k16 = 0; k16 < 2; k16++) {
            const int ku = k16 * 2 + (lane >> 4);
            uint32_t a[4][4];
            #pragma unroll
            for (int mt = 0; mt < 4; mt++) {
                const int r = wm * 64 + mt * 16 + (lane & 15);
                ldsm_x4(a[mt], aSt + (uint32_t)r * 64 + (uint32_t)((ku ^ ((r >> 1) & 3)) * 16));
            }
            uint32_t b[4][4];
            #pragma unroll
            for (int ng = 0; ng < 4; ng++) {
                const int r = wn * 64 + ng * 16 + (lane & 15);
                ldsm_x4(b[ng], bSt + (uint32_t)r * 64 + (uint32_t)((ku ^ ((r >> 1) & 3)) * 16));
            }
            #pragma unroll
            for (int mt = 0; mt < 4; mt++)
                #pragma unroll
                for (int nt = 0; nt < 8; nt++)
                    mma16816(acc[mt][nt], a[mt], b[nt >> 1][nt & 1], b[nt >> 1][(nt & 1) + 2]);
        }
        // refill stage (kt+2)%3 == (kt-1)%3: all reads of it finished before
        // this iteration's __syncthreads, so the overwrite is safe.
        if (kt + 2 < KSTEPS) issue(kt + 2, (kt + 2) % STAGES);
    }

    // epilogue
    float* C = C0 + gbase;
    #pragma unroll
    for (int mt = 0; mt < 4; mt++)
        #pragma unroll
        for (int nt = 0; nt < 8; nt++) {
            const int row = bm * 128 + wm * 64 + mt * 16 + (lane >> 2);
            const int col = bn * 128 + wn * 64 + nt * 8 + (lane & 3) * 2;
            *reinterpret_cast<float2*>(C + (size_t)row * SDIM + col) =
                make_float2(acc[mt][nt][0], acc[mt][nt][1]);
            *reinterpret_cast<float2*>(C + (size_t)(row + 8) * SDIM + col) =
                make_float2(acc[mt][nt][2], acc[mt][nt][3]);
        }
}

// ===================== launch ==============================================
extern "C" void kernel_launch(void* const* d_in, const int* in_sizes, int n_in,
                              void* d_out, int out_size) {
    const float* x1 = (const float*)d_in[0];
    const float* x2 = (const float*)d_in[1];
    float* out = (float*)d_out;
    const float4* x1v = (const float4*)x1;
    const float4* x2v = (const float4*)x2;

    // One-time stream/event resources (handles persist; the captured WORK is
    // identical on every call — deterministic, no call-count behavior).
    static cudaStream_t sC = nullptr, sS = nullptr;
    static cudaEvent_t evF = nullptr, evJS = nullptr;
    static cudaEvent_t evC[NBATCH];
    static int ready = 0;
    if (ready == 0) {
        bool ok = (cudaStreamCreateWithFlags(&sC, cudaStreamNonBlocking) == cudaSuccess) &&
                  (cudaStreamCreateWithFlags(&sS, cudaStreamNonBlocking) == cudaSuccess) &&
                  (cudaEventCreateWithFlags(&evF, cudaEventDisableTiming) == cudaSuccess) &&
                  (cudaEventCreateWithFlags(&evJS, cudaEventDisableTiming) == cudaSuccess);
        for (int g = 0; g < NBATCH && ok; g++)
            ok = (cudaEventCreateWithFlags(&evC[g], cudaEventDisableTiming) == cudaSuccess);
        ready = ok ? 1 : -1;
    }

    if (ready != 1) {
        // Fallback: fully sequential on stream 0.
        for (int g = 0; g < NBATCH; g++) {
            k_convA<<<256, 256>>>(x1v, g);
            k_convB<<<dim3(64, 64), dim3(32, 8)>>>(x2, g);
        }
        for (int g = 0; g < NBATCH; g++)
            k_gemm_mma<<<dim3(16, 16), 128>>>(out, g);
        k_init<<<1, 256>>>();
        for (int shift = 24; shift >= 0; shift -= 8) {
            k_hist<<<dim3(512, 2), 256>>>(x1v, x2v, shift);
            k_scan<<<1, 256>>>(shift);
        }
        k_maxres<<<dim3(1024, 2), 256>>>(x1v, x2v);
        k_scale<<<1, 32>>>();
        k_quant<<<dim3(1024, 2), 256>>>(x1v, x2v, (float4*)out);
        return;
    }

    // Fork conversion + stats streams off the capture origin (stream 0).
    cudaEventRecord(evF, 0);
    cudaStreamWaitEvent(sC, evF, 0);
    cudaStreamWaitEvent(sS, evF, 0);

    // ---- stream C: per-batch conversions, signal per-batch events ----
    for (int g = 0; g < NBATCH; g++) {
        k_convA<<<256, 256, 0, sC>>>(x1v, g);
        k_convB<<<dim3(64, 64), dim3(32, 8), 0, sC>>>(x2, g);
        cudaEventRecord(evC[g], sC);
    }

    // ---- stream 0: per-batch GEMMs, each gated on its conversion ----
    for (int g = 0; g < NBATCH; g++) {
        cudaStreamWaitEvent((cudaStream_t)0, evC[g], 0);
        k_gemm_mma<<<dim3(16, 16), 128>>>(out, g);
    }

    // ---- stream S: quantile + quantize -> out regions 1, 2 ----
    k_init<<<1, 256, 0, sS>>>();
    for (int shift = 24; shift >= 0; shift -= 8) {
        k_hist<<<dim3(512, 2), 256, 0, sS>>>(x1v, x2v, shift);
        k_scan<<<1, 256, 0, sS>>>(shift);
    }
    k_maxres<<<dim3(1024, 2), 256, 0, sS>>>(x1v, x2v);
    k_scale<<<1, 32, 0, sS>>>();
    k_quant<<<dim3(1024, 2), 256, 0, sS>>>(x1v, x2v, (float4*)out);

    // ---- join ----
    cudaEventRecord(evJS, sS);
    cudaStreamWaitEvent((cudaStream_t)0, evJS, 0);
}

// round 11
// speedup vs baseline: 1.0657x; 1.0657x over previous
#include <cuda_runtime.h>
#include <cuda_fp16.h>
#include <cstdint>

// Problem constants (B=2, H=8, S=2048, D=2048)
#define N_ELEM   67108864    // elements per input tensor
#define N0       33554432    // elements in x[0]
#define K_IDX    33218888u   // exact f32 quantile index of |x[0]| ascending
#define SDIM     2048
#define NBATCH   16
#define GELEMS   (SDIM * SDIM)   // elements per batch slice

// ===================== scratch: fp16 tensors (linear) =======================
__device__ __align__(1024) __half g_Ahi[N_ELEM];   // [g][m][k]  fp16(x1)
__device__ __align__(1024) __half g_Bthi[N_ELEM];  // [g][n][k]  fp16(x2^T)

// ===================== stats state (re-initialized per launch) ==============
__device__ unsigned g_hist[2][256];
__device__ unsigned g_pref[2];
__device__ unsigned g_krem[2];
__device__ unsigned g_taub[2];
__device__ unsigned g_maxres[2];
__device__ float    g_scale[2];

__global__ void k_init() {
    int i = threadIdx.x;
    g_hist[0][i] = 0; g_hist[1][i] = 0;
    if (i < 2) { g_pref[i] = 0; g_krem[i] = K_IDX; g_maxres[i] = 0; }
}

__global__ void __launch_bounds__(256) k_hist(const float4* __restrict__ x1,
                                              const float4* __restrict__ x2,
                                              int shift) {
    const int t = blockIdx.y;
    const float4* __restrict__ x = t ? x2 : x1;
    __shared__ unsigned sh[256];
    const int tid = threadIdx.x;
    sh[tid] = 0;
    __syncthreads();
    const unsigned pref = g_pref[t];
    const int n4 = N0 / 4;
    const int stride = gridDim.x * blockDim.x;
    for (int i = blockIdx.x * blockDim.x + tid; i < n4; i += stride) {
        float4 v = x[i];
        const float* f = reinterpret_cast<const float*>(&v);
        #pragma unroll
        for (int j = 0; j < 4; j++) {
            unsigned u = __float_as_uint(f[j]) & 0x7fffffffu;
            bool ok = (shift == 24) || ((u >> (shift + 8)) == pref);
            unsigned bal = __ballot_sync(0xffffffffu, ok);
            if (ok) {
                unsigned b = (u >> shift) & 255u;
                unsigned peers = __match_any_sync(bal, b);
                if ((__ffs(peers) - 1) == (tid & 31))
                    atomicAdd(&sh[b], __popc(peers));
            }
        }
    }
    __syncthreads();
    if (sh[tid]) atomicAdd(&g_hist[t][tid], sh[tid]);
}

__global__ void k_scan(int shift) {
    const int tid = threadIdx.x;
    if (tid < 2) {
        const int t = tid;
        unsigned k = g_krem[t], c = 0, chosen = 255;
        for (int b = 0; b < 256; b++) {
            unsigned h = g_hist[t][b];
            if (c + h > k) { chosen = (unsigned)b; break; }
            c += h;
        }
        g_krem[t] = k - c;
        unsigned p = (g_pref[t] << 8) | chosen;
        g_pref[t] = p;
        if (shift == 0) g_taub[t] = p;
    }
    __syncthreads();
    g_hist[0][tid] = 0; g_hist[1][tid] = 0;
}

__global__ void __launch_bounds__(256) k_maxres(const float4* __restrict__ x1,
                                                const float4* __restrict__ x2) {
    const int t = blockIdx.y;
    const float4* __restrict__ x = t ? x2 : x1;
    const unsigned taub = g_taub[t];
    const int tid = threadIdx.x;
    unsigned m = 0;
    const int n4 = N_ELEM / 4;
    const int stride = gridDim.x * blockDim.x;
    for (int i = blockIdx.x * blockDim.x + tid; i < n4; i += stride) {
        float4 v = x[i];
        const float* f = reinterpret_cast<const float*>(&v);
        #pragma unroll
        for (int j = 0; j < 4; j++) {
            unsigned u = __float_as_uint(f[j]) & 0x7fffffffu;
            if (u < taub) m = max(m, u);
        }
    }
    m = __reduce_max_sync(0xffffffffu, m);
    __shared__ unsigned sm[8];
    if ((tid & 31) == 0) sm[tid >> 5] = m;
    __syncthreads();
    if (tid == 0) {
        #pragma unroll
        for (int w = 1; w < 8; w++) m = max(m, sm[w]);
        atomicMax(&g_maxres[t], m);
    }
}

__global__ void k_scale() {
    int t = threadIdx.x;
    if (t < 2) g_scale[t] = __fdiv_rn(__uint_as_float(g_maxres[t]), 127.0f);
}

__global__ void __launch_bounds__(256) k_quant(const float4* __restrict__ x1,
                                               const float4* __restrict__ x2,
                                               float4* __restrict__ out) {
    const int t = blockIdx.y;
    const float4* __restrict__ x = t ? x2 : x1;
    float4* __restrict__ o = out + (size_t)(1 + t) * (N_ELEM / 4);
    const float tau = __uint_as_float(g_taub[t]);
    const float scale = g_scale[t];
    const int n4 = N_ELEM / 4;
    const int stride = gridDim.x * blockDim.x;
    for (int i = blockIdx.x * blockDim.x + threadIdx.x; i < n4; i += stride) {
        float4 v = x[i];
        float* f = reinterpret_cast<float*>(&v);
        #pragma unroll
        for (int j = 0; j < 4; j++) {
            float a = fabsf(f[j]);
            if (a < tau) {
                float q = rintf(__fdiv_rn(f[j], scale));
                q = fminf(fmaxf(q, -128.0f), 127.0f);
                f[j] = q * scale;
            }
        }
        o[i] = v;
    }
}

// half2 -> u32 bit cast
__device__ __forceinline__ uint32_t h2_as_u32(__half2 h) {
    union { __half2 h; uint32_t u; } c;
    c.h = h;
    return c.u;
}

// ===== A: f32 slices [g0, g0+8) -> fp16 (linear); blockIdx.z = local g ======
__global__ void __launch_bounds__(256) k_convA(const float4* __restrict__ x, int g0) {
    const int g = g0 + blockIdx.z;
    const float4* __restrict__ xs = x + (size_t)g * (GELEMS / 4);
    uint4* __restrict__ dst = reinterpret_cast<uint4*>(g_Ahi + (size_t)g * GELEMS);
    const int stride = gridDim.x * blockDim.x;
    for (int i = blockIdx.x * blockDim.x + threadIdx.x; i < GELEMS / 8; i += stride) {
        float4 v0 = xs[2 * i], v1 = xs[2 * i + 1];
        uint32_t h[4];
        h[0] = h2_as_u32(__floats2half2_rn(v0.x, v0.y));
        h[1] = h2_as_u32(__floats2half2_rn(v0.z, v0.w));
        h[2] = h2_as_u32(__floats2half2_rn(v1.x, v1.y));
        h[3] = h2_as_u32(__floats2half2_rn(v1.z, v1.w));
        dst[i] = make_uint4(h[0], h[1], h[2], h[3]);
    }
}

// ===== B: f32 slices [g0, g0+8) [k][n] -> transposed fp16 [n][k] ============
// 64x64 tile, float4 loads, smem transpose, 2 x 16B vectorized fp16 stores
// per thread (4 threads per n-row -> 64B coalesced store transactions).
__global__ void __launch_bounds__(256) k_convB(const float* __restrict__ x, int g0) {
    __shared__ float t[64][65];
    const int g = g0 + blockIdx.z;
    const float* B = x + (size_t)g * GELEMS;
    const int n0 = blockIdx.x * 64, k0 = blockIdx.y * 64;
    const int tid = threadIdx.x;

    // load 64 k-rows x 64 n-cols, float4 per thread, 4 passes
    #pragma unroll
    for (int p = 0; p < 4; p++) {
        const int idx = tid + p * 256;          // 0..1023
        const int r = idx >> 4;                  // k row
        const int c = (idx & 15) * 4;            // n col
        float4 v = *(const float4*)(B + (size_t)(k0 + r) * SDIM + n0 + c);
        t[r][c] = v.x; t[r][c + 1] = v.y; t[r][c + 2] = v.z; t[r][c + 3] = v.w;
    }
    __syncthreads();

    // output: thread -> (n_local = tid>>2, k chunk of 16 = (tid&3)*16)
    const int nl = tid >> 2, kc = (tid & 3) * 16;
    uint32_t h[8];
    #pragma unroll
    for (int i = 0; i < 8; i++)
        h[i] = h2_as_u32(__floats2half2_rn(t[kc + 2 * i][nl], t[kc + 2 * i + 1][nl]));
    __half* dst = g_Bthi + (size_t)g * GELEMS + (size_t)(n0 + nl) * SDIM + k0 + kc;
    *(uint4*)(dst)     = make_uint4(h[0], h[1], h[2], h[3]);
    *(uint4*)(dst + 8) = make_uint4(h[4], h[5], h[6], h[7]);
}

// ===== tensor-core GEMM via mma.sync (HMMA), single fp16 term ===============
// CTA 128x128, BK=32, 3-stage cp.async pipeline, 4 warps (2m x 2n),
// warp tile 64x64, mma.m16n8k16, 1 syncthreads per k-iter.
// Swizzle: 16B unit u of row r stored at u ^ ((r>>1)&3).
#define BM 128
#define BN 128
#define BK 32
#define KSTEPS 64    // 2048 / BK
#define STAGES 3

__device__ __forceinline__ uint32_t smem_u32(const void* p) {
    uint32_t a;
    asm("{ .reg .u64 t; cvta.to.shared.u64 t, %1; cvt.u32.u64 %0, t; }" : "=r"(a) : "l"(p));
    return a;
}
__device__ __forceinline__ void cp_async16(uint32_t dst, const void* src) {
    asm volatile("cp.async.cg.shared.global [%0], [%1], 16;"
                 :: "r"(dst), "l"(__cvta_generic_to_global(src)) : "memory");
}
__device__ __forceinline__ void ldsm_x4(uint32_t* r, uint32_t addr) {
    asm volatile("ldmatrix.sync.aligned.m8n8.x4.shared.b16 {%0,%1,%2,%3}, [%4];"
                 : "=r"(r[0]), "=r"(r[1]), "=r"(r[2]), "=r"(r[3]) : "r"(addr));
}
__device__ __forceinline__ void mma16816(float* d, const uint32_t* a, uint32_t b0, uint32_t b1) {
    asm volatile("mma.sync.aligned.m16n8k16.row.col.f32.f16.f16.f32 "
                 "{%0,%1,%2,%3}, {%4,%5,%6,%7}, {%8,%9}, {%0,%1,%2,%3};"
                 : "+f"(d[0]), "+f"(d[1]), "+f"(d[2]), "+f"(d[3])
                 : "r"(a[0]), "r"(a[1]), "r"(a[2]), "r"(a[3]), "r"(b0), "r"(b1));
}

__global__ void __launch_bounds__(128, 2) k_gemm_mma(float* __restrict__ C0, int g0) {
    __shared__ __align__(1024) __half As[STAGES][BM * BK];  // 3 x 8KB
    __shared__ __align__(1024) __half Bs[STAGES][BN * BK];  // 3 x 8KB

    const int tid = threadIdx.x, lane = tid & 31, w = tid >> 5;
    const int wm = w >> 1, wn = w & 1;
    const int bm = blockIdx.y, bn = blockIdx.x;
    const size_t gbase = (size_t)(g0 + blockIdx.z) * GELEMS;

    const uint32_t sA = smem_u32(As), sB = smem_u32(Bs);

    float acc[4][8][4];
    #pragma unroll
    for (int i = 0; i < 4; i++)
        #pragma unroll
        for (int j = 0; j < 8; j++)
            #pragma unroll
            for (int q = 0; q < 4; q++) acc[i][j][q] = 0.0f;

    const int ldRow = tid >> 2, ldUnit = tid & 3;   // 32 rows x 4 units per pass

    auto issue = [&](int kt, int st) {
        const __half* Abase = g_Ahi  + gbase + (size_t)(bm * 128) * SDIM + kt * 32;
        const __half* Bbase = g_Bthi + gbase + (size_t)(bn * 128) * SDIM + kt * 32;
        #pragma unroll
        for (int it = 0; it < 4; it++) {
            const int r = ldRow + it * 32;
            const uint32_t du = (uint32_t)(ldUnit ^ ((r >> 1) & 3));
            cp_async16(sA + (uint32_t)st * (BM * BK * 2) + (uint32_t)r * 64 + du * 16,
                       Abase + (size_t)r * SDIM + ldUnit * 8);
            cp_async16(sB + (uint32_t)st * (BN * BK * 2) + (uint32_t)r * 64 + du * 16,
                       Bbase + (size_t)r * SDIM + ldUnit * 8);
        }
        asm volatile("cp.async.commit_group;" ::: "memory");
    };

    issue(0, 0);
    issue(1, 1);

    for (int kt = 0; kt < KSTEPS; kt++) {
        if (kt < KSTEPS - 1)
            asm volatile("cp.async.wait_group 1;" ::: "memory");
        else
            asm volatile("cp.async.wait_group 0;" ::: "memory");
        __syncthreads();   // stage kt%3 visible to all; all reads of kt-1 done

        const int st = kt % STAGES;
        const uint32_t aSt = sA + (uint32_t)st * (BM * BK * 2);
        const uint32_t bSt = sB + (uint32_t)st * (BN * BK * 2);
        #pragma unroll
        for (int k16 = 0; k16 < 2; k16++) {
            const int ku = k16 * 2 + (lane >> 4);
            uint32_t a[4][4];
            #pragma unroll
            for (int mt = 0; mt < 4; mt++) {
                const int r = wm * 64 + mt * 16 + (lane & 15);
                ldsm_x4(a[mt], aSt + (uint32_t)r * 64 + (uint32_t)((ku ^ ((r >> 1) & 3)) * 16));
            }
            uint32_t b[4][4];
            #pragma unroll
            for (int ng = 0; ng < 4; ng++) {
                const int r = wn * 64 + ng * 16 + (lane & 15);
                ldsm_x4(b[ng], bSt + (uint32_t)r * 64 + (uint32_t)((ku ^ ((r >> 1) & 3)) * 16));
            }
            #pragma unroll
            for (int mt = 0; mt < 4; mt++)
                #pragma unroll
                for (int nt = 0; nt < 8; nt++)
                    mma16816(acc[mt][nt], a[mt], b[nt >> 1][nt & 1], b[nt >> 1][(nt & 1) + 2]);
        }
        // refill stage (kt+2)%3 == (kt-1)%3: all reads of it finished before
        // this iteration's __syncthreads, so the overwrite is safe.
        if (kt + 2 < KSTEPS) issue(kt + 2, (kt + 2) % STAGES);
    }

    // epilogue
    float* C = C0 + gbase;
    #pragma unroll
    for (int mt = 0; mt < 4; mt++)
        #pragma unroll
        for (int nt = 0; nt < 8; nt++) {
            const int row = bm * 128 + wm * 64 + mt * 16 + (lane >> 2);
            const int col = bn * 128 + wn * 64 + nt * 8 + (lane & 3) * 2;
            *reinterpret_cast<float2*>(C + (size_t)row * SDIM + col) =
                make_float2(acc[mt][nt][0], acc[mt][nt][1]);
            *reinterpret_cast<float2*>(C + (size_t)(row + 8) * SDIM + col) =
                make_float2(acc[mt][nt][2], acc[mt][nt][3]);
        }
}

// ===================== launch ==============================================
extern "C" void kernel_launch(void* const* d_in, const int* in_sizes, int n_in,
                              void* d_out, int out_size) {
    const float* x1 = (const float*)d_in[0];
    const float* x2 = (const float*)d_in[1];
    float* out = (float*)d_out;
    const float4* x1v = (const float4*)x1;
    const float4* x2v = (const float4*)x2;

    // One-time stream/event resources (handles persist; the captured WORK is
    // identical on every call — deterministic, no call-count behavior).
    static cudaStream_t sC = nullptr, sS = nullptr;
    static cudaEvent_t evF = nullptr, evH1 = nullptr, evC2 = nullptr, evJS = nullptr;
    static int ready = 0;
    if (ready == 0) {
        bool ok = (cudaStreamCreateWithFlags(&sC, cudaStreamNonBlocking) == cudaSuccess) &&
                  (cudaStreamCreateWithFlags(&sS, cudaStreamNonBlocking) == cudaSuccess) &&
                  (cudaEventCreateWithFlags(&evF, cudaEventDisableTiming) == cudaSuccess) &&
                  (cudaEventCreateWithFlags(&evH1, cudaEventDisableTiming) == cudaSuccess) &&
                  (cudaEventCreateWithFlags(&evC2, cudaEventDisableTiming) == cudaSuccess) &&
                  (cudaEventCreateWithFlags(&evJS, cudaEventDisableTiming) == cudaSuccess);
        ready = ok ? 1 : -1;
    }

    if (ready != 1) {
        // Fallback: fully sequential on stream 0.
        k_convA<<<dim3(256, 1, 8), 256>>>(x1v, 0);
        k_convA<<<dim3(256, 1, 8), 256>>>(x1v, 8);
        k_convB<<<dim3(32, 32, 8), 256>>>(x2, 0);
        k_convB<<<dim3(32, 32, 8), 256>>>(x2, 8);
        k_gemm_mma<<<dim3(16, 16, 8), 128>>>(out, 0);
        k_gemm_mma<<<dim3(16, 16, 8), 128>>>(out, 8);
        k_init<<<1, 256>>>();
        for (int shift = 24; shift >= 0; shift -= 8) {
            k_hist<<<dim3(512, 2), 256>>>(x1v, x2v, shift);
            k_scan<<<1, 256>>>(shift);
        }
        k_maxres<<<dim3(1024, 2), 256>>>(x1v, x2v);
        k_scale<<<1, 32>>>();
        k_quant<<<dim3(1024, 2), 256>>>(x1v, x2v, (float4*)out);
        return;
    }

    // Fork stats stream off the capture origin (stream 0).
    cudaEventRecord(evF, 0);
    cudaStreamWaitEvent(sS, evF, 0);

    // ---- stream 0: conv first half -> GEMM first half ----
    k_convA<<<dim3(256, 1, 8), 256>>>(x1v, 0);
    k_convB<<<dim3(32, 32, 8), 256>>>(x2, 0);
    cudaEventRecord(evH1, 0);
    // stream C: conv second half, concurrent with GEMM(0-7)
    cudaStreamWaitEvent(sC, evH1, 0);
    k_convA<<<dim3(256, 1, 8), 256, 0, sC>>>(x1v, 8);
    k_convB<<<dim3(32, 32, 8), 256, 0, sC>>>(x2, 8);
    cudaEventRecord(evC2, sC);

    k_gemm_mma<<<dim3(16, 16, 8), 128>>>(out, 0);
    cudaStreamWaitEvent((cudaStream_t)0, evC2, 0);
    k_gemm_mma<<<dim3(16, 16, 8), 128>>>(out, 8);

    // ---- stream S: quantile + quantize -> out regions 1, 2 ----
    k_init<<<1, 256, 0, sS>>>();
    for (int shift = 24; shift >= 0; shift -= 8) {
        k_hist<<<dim3(512, 2), 256, 0, sS>>>(x1v, x2v, shift);
        k_scan<<<1, 256, 0, sS>>>(shift);
    }
    k_maxres<<<dim3(1024, 2), 256, 0, sS>>>(x1v, x2v);
    k_scale<<<1, 32, 0, sS>>>();
    k_quant<<<dim3(1024, 2), 256, 0, sS>>>(x1v, x2v, (float4*)out);

    // ---- join ----
    cudaEventRecord(evJS, sS);
    cudaStreamWaitEvent((cudaStream_t)0, evJS, 0);
}

// round 13
// speedup vs baseline: 1.1346x; 1.0646x over previous
#include <cuda_runtime.h>
#include <cuda_fp16.h>
#include <cstdint>

// Problem constants (B=2, H=8, S=2048, D=2048)
#define N_ELEM   67108864    // elements per input tensor
#define N0       33554432    // elements in x[0]
#define K_IDX    33218888u   // exact f32 quantile index of |x[0]| ascending
#define SDIM     2048
#define NBATCH   16
#define GELEMS   (SDIM * SDIM)   // elements per batch slice

// ===================== scratch: fp16 tensors (linear) =======================
__device__ __align__(1024) __half g_Ahi[N_ELEM];   // [g][m][k]  fp16(x1)
__device__ __align__(1024) __half g_Bthi[N_ELEM];  // [g][n][k]  fp16(x2^T)

// ===================== stats state (re-initialized per launch) ==============
__device__ unsigned g_hist[2][256];
__device__ unsigned g_pref[2];
__device__ unsigned g_krem[2];
__device__ unsigned g_taub[2];
__device__ unsigned g_maxres[2];
__device__ float    g_scale[2];

__global__ void k_init() {
    int i = threadIdx.x;
    g_hist[0][i] = 0; g_hist[1][i] = 0;
    if (i < 2) { g_pref[i] = 0; g_krem[i] = K_IDX; g_maxres[i] = 0; }
}

__global__ void __launch_bounds__(256) k_hist(const float4* __restrict__ x1,
                                              const float4* __restrict__ x2,
                                              int shift) {
    const int t = blockIdx.y;
    const float4* __restrict__ x = t ? x2 : x1;
    __shared__ unsigned sh[256];
    const int tid = threadIdx.x;
    sh[tid] = 0;
    __syncthreads();
    const unsigned pref = g_pref[t];
    const int n4 = N0 / 4;
    const int stride = gridDim.x * blockDim.x;
    for (int i = blockIdx.x * blockDim.x + tid; i < n4; i += stride) {
        float4 v = x[i];
        const float* f = reinterpret_cast<const float*>(&v);
        #pragma unroll
        for (int j = 0; j < 4; j++) {
            unsigned u = __float_as_uint(f[j]) & 0x7fffffffu;
            bool ok = (shift == 24) || ((u >> (shift + 8)) == pref);
            unsigned bal = __ballot_sync(0xffffffffu, ok);
            if (ok) {
                unsigned b = (u >> shift) & 255u;
                unsigned peers = __match_any_sync(bal, b);
                if ((__ffs(peers) - 1) == (tid & 31))
                    atomicAdd(&sh[b], __popc(peers));
            }
        }
    }
    __syncthreads();
    if (sh[tid]) atomicAdd(&g_hist[t][tid], sh[tid]);
}

__global__ void k_scan(int shift) {
    const int tid = threadIdx.x;
    if (tid < 2) {
        const int t = tid;
        unsigned k = g_krem[t], c = 0, chosen = 255;
        for (int b = 0; b < 256; b++) {
            unsigned h = g_hist[t][b];
            if (c + h > k) { chosen = (unsigned)b; break; }
            c += h;
        }
        g_krem[t] = k - c;
        unsigned p = (g_pref[t] << 8) | chosen;
        g_pref[t] = p;
        if (shift == 0) g_taub[t] = p;
    }
    __syncthreads();
    g_hist[0][tid] = 0; g_hist[1][tid] = 0;
}

__global__ void __launch_bounds__(256) k_maxres(const float4* __restrict__ x1,
                                                const float4* __restrict__ x2) {
    const int t = blockIdx.y;
    const float4* __restrict__ x = t ? x2 : x1;
    const unsigned taub = g_taub[t];
    const int tid = threadIdx.x;
    unsigned m = 0;
    const int n4 = N_ELEM / 4;
    const int stride = gridDim.x * blockDim.x;
    for (int i = blockIdx.x * blockDim.x + tid; i < n4; i += stride) {
        float4 v = x[i];
        const float* f = reinterpret_cast<const float*>(&v);
        #pragma unroll
        for (int j = 0; j < 4; j++) {
            unsigned u = __float_as_uint(f[j]) & 0x7fffffffu;
            if (u < taub) m = max(m, u);
        }
    }
    m = __reduce_max_sync(0xffffffffu, m);
    __shared__ unsigned sm[8];
    if ((tid & 31) == 0) sm[tid >> 5] = m;
    __syncthreads();
    if (tid == 0) {
        #pragma unroll
        for (int w = 1; w < 8; w++) m = max(m, sm[w]);
        atomicMax(&g_maxres[t], m);
    }
}

__global__ void k_scale() {
    int t = threadIdx.x;
    if (t < 2) g_scale[t] = __fdiv_rn(__uint_as_float(g_maxres[t]), 127.0f);
}

__global__ void __launch_bounds__(256) k_quant(const float4* __restrict__ x1,
                                               const float4* __restrict__ x2,
                                               float4* __restrict__ out) {
    const int t = blockIdx.y;
    const float4* __restrict__ x = t ? x2 : x1;
    float4* __restrict__ o = out + (size_t)(1 + t) * (N_ELEM / 4);
    const float tau = __uint_as_float(g_taub[t]);
    const float scale = g_scale[t];
    const int n4 = N_ELEM / 4;
    const int stride = gridDim.x * blockDim.x;
    for (int i = blockIdx.x * blockDim.x + threadIdx.x; i < n4; i += stride) {
        float4 v = x[i];
        float* f = reinterpret_cast<float*>(&v);
        #pragma unroll
        for (int j = 0; j < 4; j++) {
            float a = fabsf(f[j]);
            if (a < tau) {
                float q = rintf(__fdiv_rn(f[j], scale));
                q = fminf(fmaxf(q, -128.0f), 127.0f);
                f[j] = q * scale;
            }
        }
        o[i] = v;
    }
}

// half2 -> u32 bit cast
__device__ __forceinline__ uint32_t h2_as_u32(__half2 h) {
    union { __half2 h; uint32_t u; } c;
    c.h = h;
    return c.u;
}

// ===== A: f32 slices [g0, g0+8) -> fp16 (linear); blockIdx.z = local g ======
__global__ void __launch_bounds__(256) k_convA(const float4* __restrict__ x, int g0) {
    const int g = g0 + blockIdx.z;
    const float4* __restrict__ xs = x + (size_t)g * (GELEMS / 4);
    uint4* __restrict__ dst = reinterpret_cast<uint4*>(g_Ahi + (size_t)g * GELEMS);
    const int stride = gridDim.x * blockDim.x;
    for (int i = blockIdx.x * blockDim.x + threadIdx.x; i < GELEMS / 8; i += stride) {
        float4 v0 = xs[2 * i], v1 = xs[2 * i + 1];
        uint32_t h[4];
        h[0] = h2_as_u32(__floats2half2_rn(v0.x, v0.y));
        h[1] = h2_as_u32(__floats2half2_rn(v0.z, v0.w));
        h[2] = h2_as_u32(__floats2half2_rn(v1.x, v1.y));
        h[3] = h2_as_u32(__floats2half2_rn(v1.z, v1.w));
        dst[i] = make_uint4(h[0], h[1], h[2], h[3]);
    }
}

// ===== B: f32 slices [g0, g0+8) [k][n] -> transposed fp16 [n][k] ============
__global__ void __launch_bounds__(256) k_convB(const float* __restrict__ x, int g0) {
    __shared__ float t[64][65];
    const int g = g0 + blockIdx.z;
    const float* B = x + (size_t)g * GELEMS;
    const int n0 = blockIdx.x * 64, k0 = blockIdx.y * 64;
    const int tid = threadIdx.x;

    #pragma unroll
    for (int p = 0; p < 4; p++) {
        const int idx = tid + p * 256;
        const int r = idx >> 4;
        const int c = (idx & 15) * 4;
        float4 v = *(const float4*)(B + (size_t)(k0 + r) * SDIM + n0 + c);
        t[r][c] = v.x; t[r][c + 1] = v.y; t[r][c + 2] = v.z; t[r][c + 3] = v.w;
    }
    __syncthreads();

    const int nl = tid >> 2, kc = (tid & 3) * 16;
    uint32_t h[8];
    #pragma unroll
    for (int i = 0; i < 8; i++)
        h[i] = h2_as_u32(__floats2half2_rn(t[kc + 2 * i][nl], t[kc + 2 * i + 1][nl]));
    __half* dst = g_Bthi + (size_t)g * GELEMS + (size_t)(n0 + nl) * SDIM + k0 + kc;
    *(uint4*)(dst)     = make_uint4(h[0], h[1], h[2], h[3]);
    *(uint4*)(dst + 8) = make_uint4(h[4], h[5], h[6], h[7]);
}

// ===================== shared GEMM building blocks ==========================
__device__ __forceinline__ uint32_t smem_u32(const void* p) {
    uint32_t a;
    asm("{ .reg .u64 t; cvta.to.shared.u64 t, %1; cvt.u32.u64 %0, t; }" : "=r"(a) : "l"(p));
    return a;
}
__device__ __forceinline__ void cp_async16(uint32_t dst, const void* src) {
    asm volatile("cp.async.cg.shared.global [%0], [%1], 16;"
                 :: "r"(dst), "l"(__cvta_generic_to_global(src)) : "memory");
}
__device__ __forceinline__ void ldsm_x4(uint32_t* r, uint32_t addr) {
    asm volatile("ldmatrix.sync.aligned.m8n8.x4.shared.b16 {%0,%1,%2,%3}, [%4];"
                 : "=r"(r[0]), "=r"(r[1]), "=r"(r[2]), "=r"(r[3]) : "r"(addr));
}
__device__ __forceinline__ void mma16816(float* d, const uint32_t* a, uint32_t b0, uint32_t b1) {
    asm volatile("mma.sync.aligned.m16n8k16.row.col.f32.f16.f16.f32 "
                 "{%0,%1,%2,%3}, {%4,%5,%6,%7}, {%8,%9}, {%0,%1,%2,%3};"
                 : "+f"(d[0]), "+f"(d[1]), "+f"(d[2]), "+f"(d[3])
                 : "r"(a[0]), "r"(a[1]), "r"(a[2]), "r"(a[3]), "r"(b0), "r"(b1));
}

// ===== GEMM variant 1: BK=64, 3-stage, 96KB dynamic smem ====================
// Rows 128B (8 x 16B units); unit u of row r stored at u ^ (r & 7).
#define STAGE_A64   (128 * 64 * 2)        // 16384 B
#define STAGE_BYT64 (2 * STAGE_A64)       // 32768 B
#define GEMM_SMEM64 (3 * STAGE_BYT64)     // 98304 B

__global__ void __launch_bounds__(128, 2) k_gemm64(float* __restrict__ C0, int g0) {
    extern __shared__ __align__(16) char smem[];
    const uint32_t sbase = smem_u32(smem);

    const int tid = threadIdx.x, lane = tid & 31, w = tid >> 5;
    const int wm = w >> 1, wn = w & 1;
    const int bm = blockIdx.y, bn = blockIdx.x;
    const size_t gbase = (size_t)(g0 + blockIdx.z) * GELEMS;

    float acc[4][8][4];
    #pragma unroll
    for (int i = 0; i < 4; i++)
        #pragma unroll
        for (int j = 0; j < 8; j++)
            #pragma unroll
            for (int q = 0; q < 4; q++) acc[i][j][q] = 0.0f;

    const int ldRow = tid >> 3, ldUnit = tid & 7;   // 16 rows x 8 units per pass

    auto issue = [&](int kt, int st) {
        const __half* Abase = g_Ahi  + gbase + (size_t)(bm * 128) * SDIM + kt * 64;
        const __half* Bbase = g_Bthi + gbase + (size_t)(bn * 128) * SDIM + kt * 64;
        const uint32_t sA = sbase + (uint32_t)st * STAGE_BYT64;
        const uint32_t sB = sA + STAGE_A64;
        #pragma unroll
        for (int it = 0; it < 8; it++) {
            const int r = ldRow + it * 16;
            const uint32_t du = (uint32_t)(ldUnit ^ (r & 7));
            cp_async16(sA + (uint32_t)r * 128 + du * 16,
                       Abase + (size_t)r * SDIM + ldUnit * 8);
            cp_async16(sB + (uint32_t)r * 128 + du * 16,
                       Bbase + (size_t)r * SDIM + ldUnit * 8);
        }
        asm volatile("cp.async.commit_group;" ::: "memory");
    };

    issue(0, 0);
    issue(1, 1);

    for (int kt = 0; kt < 32; kt++) {
        if (kt < 31)
            asm volatile("cp.async.wait_group 1;" ::: "memory");
        else
            asm volatile("cp.async.wait_group 0;" ::: "memory");
        __syncthreads();

        const int st = kt % 3;
        const uint32_t aSt = sbase + (uint32_t)st * STAGE_BYT64;
        const uint32_t bSt = aSt + STAGE_A64;
        #pragma unroll
        for (int k16 = 0; k16 < 4; k16++) {
            const int ku = k16 * 2 + (lane >> 4);
            uint32_t a[4][4];
            #pragma unroll
            for (int mt = 0; mt < 4; mt++) {
                const int r = wm * 64 + mt * 16 + (lane & 15);
                ldsm_x4(a[mt], aSt + (uint32_t)r * 128 + (uint32_t)((ku ^ (r & 7)) * 16));
            }
            uint32_t b[4][4];
            #pragma unroll
            for (int ng = 0; ng < 4; ng++) {
                const int r = wn * 64 + ng * 16 + (lane & 15);
                ldsm_x4(b[ng], bSt + (uint32_t)r * 128 + (uint32_t)((ku ^ (r & 7)) * 16));
            }
            #pragma unroll
            for (int mt = 0; mt < 4; mt++)
                #pragma unroll
                for (int nt = 0; nt < 8; nt++)
                    mma16816(acc[mt][nt], a[mt], b[nt >> 1][nt & 1], b[nt >> 1][(nt & 1) + 2]);
        }
        if (kt + 2 < 32) issue(kt + 2, (kt + 2) % 3);
    }

    float* C = C0 + gbase;
    #pragma unroll
    for (int mt = 0; mt < 4; mt++)
        #pragma unroll
        for (int nt = 0; nt < 8; nt++) {
            const int row = bm * 128 + wm * 64 + mt * 16 + (lane >> 2);
            const int col = bn * 128 + wn * 64 + nt * 8 + (lane & 3) * 2;
            *reinterpret_cast<float2*>(C + (size_t)row * SDIM + col) =
                make_float2(acc[mt][nt][0], acc[mt][nt][1]);
            *reinterpret_cast<float2*>(C + (size_t)(row + 8) * SDIM + col) =
                make_float2(acc[mt][nt][2], acc[mt][nt][3]);
        }
}

// ===== GEMM variant 2 (fallback, proven R11): BK=32, 48KB static ============
__global__ void __launch_bounds__(128, 2) k_gemm32(float* __restrict__ C0, int g0) {
    __shared__ __align__(1024) __half As[3][128 * 32];
    __shared__ __align__(1024) __half Bs[3][128 * 32];

    const int tid = threadIdx.x, lane = tid & 31, w = tid >> 5;
    const int wm = w >> 1, wn = w & 1;
    const int bm = blockIdx.y, bn = blockIdx.x;
    const size_t gbase = (size_t)(g0 + blockIdx.z) * GELEMS;

    const uint32_t sA = smem_u32(As), sB = smem_u32(Bs);

    float acc[4][8][4];
    #pragma unroll
    for (int i = 0; i < 4; i++)
        #pragma unroll
        for (int j = 0; j < 8; j++)
            #pragma unroll
            for (int q = 0; q < 4; q++) acc[i][j][q] = 0.0f;

    const int ldRow = tid >> 2, ldUnit = tid & 3;

    auto issue = [&](int kt, int st) {
        const __half* Abase = g_Ahi  + gbase + (size_t)(bm * 128) * SDIM + kt * 32;
        const __half* Bbase = g_Bthi + gbase + (size_t)(bn * 128) * SDIM + kt * 32;
        #pragma unroll
        for (int it = 0; it < 4; it++) {
            const int r = ldRow + it * 32;
            const uint32_t du = (uint32_t)(ldUnit ^ ((r >> 1) & 3));
            cp_async16(sA + (uint32_t)st * (128 * 32 * 2) + (uint32_t)r * 64 + du * 16,
                       Abase + (size_t)r * SDIM + ldUnit * 8);
            cp_async16(sB + (uint32_t)st * (128 * 32 * 2) + (uint32_t)r * 64 + du * 16,
                       Bbase + (size_t)r * SDIM + ldUnit * 8);
        }
        asm volatile("cp.async.commit_group;" ::: "memory");
    };

    issue(0, 0);
    issue(1, 1);

    for (int kt = 0; kt < 64; kt++) {
        if (kt < 63)
            asm volatile("cp.async.wait_group 1;" ::: "memory");
        else
            asm volatile("cp.async.wait_group 0;" ::: "memory");
        __syncthreads();

        const int st = kt % 3;
        const uint32_t aSt = sA + (uint32_t)st * (128 * 32 * 2);
        const uint32_t bSt = sB + (uint32_t)st * (128 * 32 * 2);
        #pragma unroll
        for (int k16 = 0; k16 < 2; k16++) {
            const int ku = k16 * 2 + (lane >> 4);
            uint32_t a[4][4];
            #pragma unroll
            for (int mt = 0; mt < 4; mt++) {
                const int r = wm * 64 + mt * 16 + (lane & 15);
                ldsm_x4(a[mt], aSt + (uint32_t)r * 64 + (uint32_t)((ku ^ ((r >> 1) & 3)) * 16));
            }
            uint32_t b[4][4];
            #pragma unroll
            for (int ng = 0; ng < 4; ng++) {
                const int r = wn * 64 + ng * 16 + (lane & 15);
                ldsm_x4(b[ng], bSt + (uint32_t)r * 64 + (uint32_t)((ku ^ ((r >> 1) & 3)) * 16));
            }
            #pragma unroll
            for (int mt = 0; mt < 4; mt++)
                #pragma unroll
                for (int nt = 0; nt < 8; nt++)
                    mma16816(acc[mt][nt], a[mt], b[nt >> 1][nt & 1], b[nt >> 1][(nt & 1) + 2]);
        }
        if (kt + 2 < 64) issue(kt + 2, (kt + 2) % 3);
    }

    float* C = C0 + gbase;
    #pragma unroll
    for (int mt = 0; mt < 4; mt++)
        #pragma unroll
        for (int nt = 0; nt < 8; nt++) {
            const int row = bm * 128 + wm * 64 + mt * 16 + (lane >> 2);
            const int col = bn * 128 + wn * 64 + nt * 8 + (lane & 3) * 2;
            *reinterpret_cast<float2*>(C + (size_t)row * SDIM + col) =
                make_float2(acc[mt][nt][0], acc[mt][nt][1]);
            *reinterpret_cast<float2*>(C + (size_t)(row + 8) * SDIM + col) =
                make_float2(acc[mt][nt][2], acc[mt][nt][3]);
        }
}

// ===================== launch ==============================================
static inline void launch_gemm(bool use64, float* out, int g0, cudaStream_t s) {
    if (use64)
        k_gemm64<<<dim3(16, 16, 8), 128, GEMM_SMEM64, s>>>(out, g0);
    else
        k_gemm32<<<dim3(16, 16, 8), 128, 0, s>>>(out, g0);
}

extern "C" void kernel_launch(void* const* d_in, const int* in_sizes, int n_in,
                              void* d_out, int out_size) {
    const float* x1 = (const float*)d_in[0];
    const float* x2 = (const float*)d_in[1];
    float* out = (float*)d_out;
    const float4* x1v = (const float4*)x1;
    const float4* x2v = (const float4*)x2;

    // Checked, idempotent opt-in for 96KB dynamic smem. Deterministic per
    // process: same result every call.
    cudaError_t rcAttr = cudaFuncSetAttribute(
        k_gemm64, cudaFuncAttributeMaxDynamicSharedMemorySize, GEMM_SMEM64);
    const bool use64 = (rcAttr == cudaSuccess);

    // One-time stream/event resources (handles persist; captured WORK is
    // identical on every call).
    static cudaStream_t sC = nullptr, sS = nullptr;
    static cudaEvent_t evF = nullptr, evH1 = nullptr, evC2 = nullptr, evJS = nullptr;
    static int ready = 0;
    if (ready == 0) {
        bool ok = (cudaStreamCreateWithFlags(&sC, cudaStreamNonBlocking) == cudaSuccess) &&
                  (cudaStreamCreateWithFlags(&sS, cudaStreamNonBlocking) == cudaSuccess) &&
                  (cudaEventCreateWithFlags(&evF, cudaEventDisableTiming) == cudaSuccess) &&
                  (cudaEventCreateWithFlags(&evH1, cudaEventDisableTiming) == cudaSuccess) &&
                  (cudaEventCreateWithFlags(&evC2, cudaEventDisableTiming) == cudaSuccess) &&
                  (cudaEventCreateWithFlags(&evJS, cudaEventDisableTiming) == cudaSuccess);
        ready = ok ? 1 : -1;
    }

    if (ready != 1) {
        // Fallback: fully sequential on stream 0.
        k_convA<<<dim3(256, 1, 8), 256>>>(x1v, 0);
        k_convA<<<dim3(256, 1, 8), 256>>>(x1v, 8);
        k_convB<<<dim3(32, 32, 8), 256>>>(x2, 0);
        k_convB<<<dim3(32, 32, 8), 256>>>(x2, 8);
        launch_gemm(use64, out, 0, 0);
        launch_gemm(use64, out, 8, 0);
        k_init<<<1, 256>>>();
        for (int shift = 24; shift >= 0; shift -= 8) {
            k_hist<<<dim3(512, 2), 256>>>(x1v, x2v, shift);
            k_scan<<<1, 256>>>(shift);
        }
        k_maxres<<<dim3(1024, 2), 256>>>(x1v, x2v);
        k_scale<<<1, 32>>>();
        k_quant<<<dim3(1024, 2), 256>>>(x1v, x2v, (float4*)out);
        return;
    }

    // Fork stats stream off the capture origin (stream 0).
    cudaEventRecord(evF, 0);
    cudaStreamWaitEvent(sS, evF, 0);

    // ---- stream 0: conv first half -> GEMM first half ----
    k_convA<<<dim3(256, 1, 8), 256>>>(x1v, 0);
    k_convB<<<dim3(32, 32, 8), 256>>>(x2, 0);
    cudaEventRecord(evH1, 0);
    // stream C: conv second half, concurrent with GEMM(0-7)
    cudaStreamWaitEvent(sC, evH1, 0);
    k_convA<<<dim3(256, 1, 8), 256, 0, sC>>>(x1v, 8);
    k_convB<<<dim3(32, 32, 8), 256, 0, sC>>>(x2, 8);
    cudaEventRecord(evC2, sC);

    launch_gemm(use64, out, 0, 0);
    cudaStreamWaitEvent((cudaStream_t)0, evC2, 0);
    launch_gemm(use64, out, 8, 0);

    // ---- stream S: quantile + quantize -> out regions 1, 2 ----
    k_init<<<1, 256, 0, sS>>>();
    for (int shift = 24; shift >= 0; shift -= 8) {
        k_hist<<<dim3(512, 2), 256, 0, sS>>>(x1v, x2v, shift);
        k_scan<<<1, 256, 0, sS>>>(shift);
    }
    k_maxres<<<dim3(1024, 2), 256, 0, sS>>>(x1v, x2v);
    k_scale<<<1, 32, 0, sS>>>();
    k_quant<<<dim3(1024, 2), 256, 0, sS>>>(x1v, x2v, (float4*)out);

    // ---- join ----
    cudaEventRecord(evJS, sS);
    cudaStreamWaitEvent((cudaStream_t)0, evJS, 0);
}